// round 1
// baseline (speedup 1.0000x reference)
#include <cuda_runtime.h>
#include <cstdint>
#include <cstdio>

// Problem constants
#define NB 64
#define NL 64
#define NC 16
#define DM 450          // EMB(300) + 3*50
#define NTOK 8192       // 2 * B * L
// char-table: widths 3,4,5 ; 100 vocab ; 50 filters
// M layout per width: [k][v][f] ; offsets 0 / 15000 / 35000 ; total 60000

__device__ float g_x[(size_t)NTOK * DM];
__device__ float g_y[(size_t)NTOK * DM];
__device__ float g_M[60000];

// ---------------------------------------------------------------------------
// 1) Precompute char tables: M[k][v][f] = sum_ch cemb[v][ch] * w[f][ch][k]
// ---------------------------------------------------------------------------
__global__ void precomp_kernel(const float* __restrict__ cemb,
                               const float* __restrict__ w3,
                               const float* __restrict__ w4,
                               const float* __restrict__ w5) {
    int idx = blockIdx.x * blockDim.x + threadIdx.x;
    if (idx >= 60000) return;
    const float* W;
    int WD, local;
    if (idx < 15000)      { W = w3; WD = 3; local = idx; }
    else if (idx < 35000) { W = w4; WD = 4; local = idx - 15000; }
    else                  { W = w5; WD = 5; local = idx - 35000; }
    int f  = local % 50;
    int kv = local / 50;
    int v  = kv % 100;
    int k  = kv / 100;
    const float* e  = cemb + v * 64;
    const float* wp = W + (size_t)f * 64 * WD + k;   // w[f][ch][k], ch stride WD
    float s = 0.f;
#pragma unroll 8
    for (int ch = 0; ch < 64; ch++) s += e[ch] * wp[ch * WD];
    g_M[idx] = s;
}

// ---------------------------------------------------------------------------
// 2) Embedding + char features -> g_x[tok][450]
//    one block per token, 160 threads
// ---------------------------------------------------------------------------
__global__ void embed_kernel(const int* __restrict__ q1, const int* __restrict__ q2,
                             const int* __restrict__ q1c, const int* __restrict__ q2c,
                             const float* __restrict__ wemb,
                             const float* __restrict__ b3, const float* __restrict__ b4,
                             const float* __restrict__ b5) {
    int tok = blockIdx.x;
    int r   = tok >> 12;         // branch
    int li  = tok & 4095;        // b*64 + l
    const int* q  = r ? q2 : q1;
    const int* qc = r ? q2c : q1c;
    int tid = threadIdx.x;

    __shared__ int ids[16];
    if (tid < 16) ids[tid] = qc[li * 16 + tid];
    __syncthreads();

    float* xrow = g_x + (size_t)tok * DM;
    const float* we = wemb + (size_t)q[li] * 300;
    for (int i = tid; i < 300; i += blockDim.x) xrow[i] = we[i];

    int f = tid;
    if (f < 150) {
        int fi, base, wd;
        float bias;
        if (f < 50)       { wd = 3; fi = f;       base = 0;     bias = b3[fi]; }
        else if (f < 100) { wd = 4; fi = f - 50;  base = 15000; bias = b4[fi]; }
        else              { wd = 5; fi = f - 100; base = 35000; bias = b5[fi]; }
        float m = 0.f;                 // relu then max == max(0, max_t h)
        int tout = 16 - wd + 1;
        for (int t = 0; t < tout; t++) {
            float h = bias;
            for (int k = 0; k < wd; k++)
                h += g_M[base + (k * 100 + ids[t + k]) * 50 + fi];
            m = fmaxf(m, h);
        }
        xrow[300 + f] = m;
    }
}

// ---------------------------------------------------------------------------
// 3) Highway layer: y = x @ W^T + b ; out = sig(y)*relu(y) + (1-sig(y))*x
//    GEMM M=8192 N=450 K=450.  dir=0: g_x->g_y, dir=1: g_y->g_x
// ---------------------------------------------------------------------------
#define HBM 128
#define HBN 64
#define HBK 16

__global__ __launch_bounds__(256) void highway_kernel(int dir,
        const float* __restrict__ W, const float* __restrict__ bias) {
    const float* X = dir ? g_y : g_x;
    float* OUT     = dir ? g_x : g_y;
    __shared__ float As[HBK][HBM + 4];
    __shared__ float Bs[HBK][HBN + 4];
    int bm = blockIdx.y * HBM;
    int bn = blockIdx.x * HBN;
    int tid = threadIdx.x;
    int tm = (tid >> 4) * 8;
    int tn = (tid & 15) * 4;
    float acc[8][4] = {};

    for (int k0 = 0; k0 < DM; k0 += HBK) {
        for (int idx = tid; idx < HBM * HBK; idx += 256) {
            int m = idx >> 4, k = idx & 15;
            int kk = k0 + k;
            As[k][m] = (kk < DM) ? X[(size_t)(bm + m) * DM + kk] : 0.f;
        }
        for (int idx = tid; idx < HBN * HBK; idx += 256) {
            int n = idx >> 4, k = idx & 15;
            int kk = k0 + k;
            float v = 0.f;
            if (kk < DM && bn + n < DM) v = W[(size_t)(bn + n) * DM + kk];
            Bs[k][n] = v;
        }
        __syncthreads();
#pragma unroll
        for (int k = 0; k < HBK; k++) {
            float4 a0 = *(const float4*)&As[k][tm];
            float4 a1 = *(const float4*)&As[k][tm + 4];
            float4 bv = *(const float4*)&Bs[k][tn];
            float a[8] = {a0.x, a0.y, a0.z, a0.w, a1.x, a1.y, a1.z, a1.w};
            float b[4] = {bv.x, bv.y, bv.z, bv.w};
#pragma unroll
            for (int i = 0; i < 8; i++)
#pragma unroll
                for (int j = 0; j < 4; j++)
                    acc[i][j] += a[i] * b[j];
        }
        __syncthreads();
    }

#pragma unroll
    for (int i = 0; i < 8; i++) {
        int m = bm + tm + i;
#pragma unroll
        for (int j = 0; j < 4; j++) {
            int n = bn + tn + j;
            if (n < DM) {
                float y = acc[i][j] + bias[n];
                float g = 1.f / (1.f + __expf(-y));
                float xv = X[(size_t)m * DM + n];
                OUT[(size_t)m * DM + n] = g * fmaxf(y, 0.f) + (1.f - g) * xv;
            }
        }
    }
}

// ---------------------------------------------------------------------------
// 4) Self-attention. One block per (branch, b). d-tiled in smem.
//    scores[i][j] = s1[i] + s2[j] + sum_d x[i,d]*w3[d]*x[j,d] + b
//    logits = (j < len) ? scores : -1e-9   (soft mask, matches reference!)
//    att = softmax(logits) @ x ;  last ? out=att : x += att (in place)
// ---------------------------------------------------------------------------
__global__ __launch_bounds__(256) void attn_kernel(
        const int* __restrict__ q1_len, const int* __restrict__ q2_len,
        const float* __restrict__ attw, const float* __restrict__ attb,
        int it, int last, float* __restrict__ dout) {
    int batch = blockIdx.x;
    int r = batch >> 6, b = batch & 63;
    int len = (r ? q2_len : q1_len)[b];
    const float* aw = attw + it * 1350;
    float ab = attb[it];
    float* X = g_x + (size_t)batch * 64 * DM;

    __shared__ float xs[64][68];
    __shared__ float sc[64][65];
    __shared__ float s1[64], s2[64], w3s[64];

    int tid  = threadIdx.x;
    int warp = tid >> 5, lane = tid & 31;
    if (tid < 64) { s1[tid] = 0.f; s2[tid] = 0.f; }

    int ti = (tid >> 4) << 2;
    int tj = (tid & 15) << 2;
    float accs[4][4] = {};

    // ---- Phase A: scores + s1/s2, accumulated over d-tiles ----
    for (int d0 = 0; d0 < DM; d0 += 64) {
        int dn = min(64, DM - d0);
        __syncthreads();
        for (int idx = tid; idx < 64 * 64; idx += 256) {
            int row = idx >> 6, d = idx & 63;
            xs[row][d] = (d < dn) ? X[row * DM + d0 + d] : 0.f;
        }
        if (tid < 64) w3s[tid] = (tid < dn) ? aw[900 + d0 + tid] : 0.f;
        __syncthreads();

        // s1, s2 partial dots (warp w owns rows 8w..8w+7)
#pragma unroll
        for (int rr = 0; rr < 8; rr++) {
            int row = warp * 8 + rr;
            float a1 = 0.f, a2 = 0.f;
            for (int d = lane; d < dn; d += 32) {
                float xv = xs[row][d];
                a1 += xv * aw[d0 + d];
                a2 += xv * aw[450 + d0 + d];
            }
#pragma unroll
            for (int off = 16; off > 0; off >>= 1) {
                a1 += __shfl_down_sync(0xffffffffu, a1, off);
                a2 += __shfl_down_sync(0xffffffffu, a2, off);
            }
            if (lane == 0) { s1[row] += a1; s2[row] += a2; }
        }

        // (x*w3) @ x^T partial, 4x4 register tile
        for (int d = 0; d < 64; d++) {
            float w3v = w3s[d];
            float av[4], bv[4];
#pragma unroll
            for (int i = 0; i < 4; i++) av[i] = xs[ti + i][d] * w3v;
#pragma unroll
            for (int j = 0; j < 4; j++) bv[j] = xs[tj + j][d];
#pragma unroll
            for (int i = 0; i < 4; i++)
#pragma unroll
                for (int j = 0; j < 4; j++)
                    accs[i][j] += av[i] * bv[j];
        }
    }
#pragma unroll
    for (int i = 0; i < 4; i++)
#pragma unroll
        for (int j = 0; j < 4; j++)
            sc[ti + i][tj + j] = accs[i][j];
    __syncthreads();

    // ---- Phase B: softmax per row (soft mask -1e-9, included in softmax) ----
#pragma unroll
    for (int rr = 0; rr < 8; rr++) {
        int row = warp * 8 + rr;
        float v0 = sc[row][lane]      + s1[row] + s2[lane]      + ab;
        float v1 = sc[row][lane + 32] + s1[row] + s2[lane + 32] + ab;
        float l0 = (lane      < len) ? v0 : -1e-9f;
        float l1 = (lane + 32 < len) ? v1 : -1e-9f;
        float mx = fmaxf(l0, l1);
#pragma unroll
        for (int off = 16; off > 0; off >>= 1)
            mx = fmaxf(mx, __shfl_xor_sync(0xffffffffu, mx, off));
        float e0 = __expf(l0 - mx), e1 = __expf(l1 - mx);
        float s = e0 + e1;
#pragma unroll
        for (int off = 16; off > 0; off >>= 1)
            s += __shfl_xor_sync(0xffffffffu, s, off);
        float inv = 1.f / s;
        sc[row][lane]      = e0 * inv;
        sc[row][lane + 32] = e1 * inv;
    }
    __syncthreads();

    // ---- Phase C: att = P @ x, tiled over d; write out / residual ----
    for (int d0 = 0; d0 < DM; d0 += 64) {
        int dn = min(64, DM - d0);
        for (int idx = tid; idx < 64 * 64; idx += 256) {
            int row = idx >> 6, d = idx & 63;
            xs[row][d] = (d < dn) ? X[row * DM + d0 + d] : 0.f;
        }
        __syncthreads();
        float acco[4][4] = {};
        for (int j = 0; j < 64; j++) {
            float pv[4], xv[4];
#pragma unroll
            for (int i = 0; i < 4; i++) pv[i] = sc[ti + i][j];
#pragma unroll
            for (int dd = 0; dd < 4; dd++) xv[dd] = xs[j][tj + dd];
#pragma unroll
            for (int i = 0; i < 4; i++)
#pragma unroll
                for (int dd = 0; dd < 4; dd++)
                    acco[i][dd] += pv[i] * xv[dd];
        }
#pragma unroll
        for (int i = 0; i < 4; i++) {
            int row = ti + i;
#pragma unroll
            for (int dd = 0; dd < 4; dd++) {
                int d = d0 + tj + dd;
                if (d < DM) {
                    if (last)
                        dout[((size_t)batch * 64 + row) * DM + d] = acco[i][dd];
                    else
                        X[row * DM + d] = acco[i][dd] + xs[row][tj + dd];
                }
            }
        }
        __syncthreads();
    }
}

// ---------------------------------------------------------------------------
extern "C" void kernel_launch(void* const* d_in, const int* in_sizes, int n_in,
                              void* d_out, int out_size) {
    const int*   q1     = (const int*)d_in[0];
    const int*   q2     = (const int*)d_in[1];
    const int*   q1_len = (const int*)d_in[2];
    const int*   q2_len = (const int*)d_in[3];
    const int*   q1c    = (const int*)d_in[4];
    const int*   q2c    = (const int*)d_in[5];
    const float* wemb   = (const float*)d_in[6];
    const float* cemb   = (const float*)d_in[7];
    const float* cw3    = (const float*)d_in[8];
    const float* cb3    = (const float*)d_in[9];
    const float* cw4    = (const float*)d_in[10];
    const float* cb4    = (const float*)d_in[11];
    const float* cw5    = (const float*)d_in[12];
    const float* cb5    = (const float*)d_in[13];
    const float* hw_w   = (const float*)d_in[14];
    const float* hw_b   = (const float*)d_in[15];
    const float* attw   = (const float*)d_in[16];
    const float* attb   = (const float*)d_in[17];
    float* out = (float*)d_out;

    precomp_kernel<<<(60000 + 255) / 256, 256>>>(cemb, cw3, cw4, cw5);
    embed_kernel<<<NTOK, 160>>>(q1, q2, q1c, q2c, wemb, cb3, cb4, cb5);
    highway_kernel<<<dim3(8, 64), 256>>>(0, hw_w, hw_b);   // g_x -> g_y
    highway_kernel<<<dim3(8, 64), 256>>>(1, hw_w, hw_b);   // g_y -> g_x
    attn_kernel<<<128, 256>>>(q1_len, q2_len, attw, attb, 0, 0, out);
    attn_kernel<<<128, 256>>>(q1_len, q2_len, attw, attb, 1, 1, out);
}

// round 2
// speedup vs baseline: 1.8042x; 1.8042x over previous
#include <cuda_runtime.h>
#include <cstdint>

// Problem constants
#define NB 64
#define NL 64
#define NC 16
#define DM 450          // EMB(300) + 3*50
#define NTOK 8192       // 2 * B * L

typedef unsigned long long ull;

__device__ __forceinline__ ull pk2(float lo, float hi) {
    ull r; asm("mov.b64 %0, {%1, %2};" : "=l"(r) : "f"(lo), "f"(hi)); return r;
}
__device__ __forceinline__ void upk2(ull v, float& lo, float& hi) {
    asm("mov.b64 {%0, %1}, %2;" : "=f"(lo), "=f"(hi) : "l"(v));
}
__device__ __forceinline__ void fma2(ull& d, ull a, ull b) {
    asm("fma.rn.f32x2 %0, %1, %2, %0;" : "+l"(d) : "l"(a), "l"(b));
}

__device__ float g_x[(size_t)NTOK * DM];
__device__ float g_y[(size_t)NTOK * DM];
__device__ float g_M[60000];

// ---------------------------------------------------------------------------
// 1) Precompute char tables: M[k][v][f] = sum_ch cemb[v][ch] * w[f][ch][k]
// ---------------------------------------------------------------------------
__global__ void precomp_kernel(const float* __restrict__ cemb,
                               const float* __restrict__ w3,
                               const float* __restrict__ w4,
                               const float* __restrict__ w5) {
    int idx = blockIdx.x * blockDim.x + threadIdx.x;
    if (idx >= 60000) return;
    const float* W;
    int WD, local;
    if (idx < 15000)      { W = w3; WD = 3; local = idx; }
    else if (idx < 35000) { W = w4; WD = 4; local = idx - 15000; }
    else                  { W = w5; WD = 5; local = idx - 35000; }
    int f  = local % 50;
    int kv = local / 50;
    int v  = kv % 100;
    int k  = kv / 100;
    const float* e  = cemb + v * 64;
    const float* wp = W + (size_t)f * 64 * WD + k;
    float s = 0.f;
#pragma unroll 8
    for (int ch = 0; ch < 64; ch++) s += e[ch] * wp[ch * WD];
    g_M[idx] = s;
}

// ---------------------------------------------------------------------------
// 2) Embedding + char features -> g_x[tok][450]
// ---------------------------------------------------------------------------
__global__ void embed_kernel(const int* __restrict__ q1, const int* __restrict__ q2,
                             const int* __restrict__ q1c, const int* __restrict__ q2c,
                             const float* __restrict__ wemb,
                             const float* __restrict__ b3, const float* __restrict__ b4,
                             const float* __restrict__ b5) {
    int tok = blockIdx.x;
    int r   = tok >> 12;
    int li  = tok & 4095;
    const int* q  = r ? q2 : q1;
    const int* qc = r ? q2c : q1c;
    int tid = threadIdx.x;

    __shared__ int ids[16];
    if (tid < 16) ids[tid] = qc[li * 16 + tid];
    __syncthreads();

    float* xrow = g_x + (size_t)tok * DM;
    const float* we = wemb + (size_t)q[li] * 300;
    for (int i = tid; i < 300; i += blockDim.x) xrow[i] = we[i];

    int f = tid;
    if (f < 150) {
        int fi, base, wd;
        float bias;
        if (f < 50)       { wd = 3; fi = f;       base = 0;     bias = b3[fi]; }
        else if (f < 100) { wd = 4; fi = f - 50;  base = 15000; bias = b4[fi]; }
        else              { wd = 5; fi = f - 100; base = 35000; bias = b5[fi]; }
        float m = 0.f;
        int tout = 16 - wd + 1;
        for (int t = 0; t < tout; t++) {
            float h = bias;
            for (int k = 0; k < wd; k++)
                h += g_M[base + (k * 100 + ids[t + k]) * 50 + fi];
            m = fmaxf(m, h);
        }
        xrow[300 + f] = m;
    }
}

// ---------------------------------------------------------------------------
// 3) Highway: y = x @ W^T + b ; out = sig(y)*relu(y) + (1-sig(y))*x
//    GEMM M=8192 N=450 K=450, f32x2 packed FMA, 128x64 tile, 1 wave.
// ---------------------------------------------------------------------------
#define HBM 128
#define HBN 64
#define HBK 16

__global__ __launch_bounds__(256, 4) void highway_kernel(int dir,
        const float* __restrict__ W, const float* __restrict__ bias) {
    const float* X = dir ? g_y : g_x;
    float* OUT     = dir ? g_x : g_y;
    __shared__ float As[HBK][HBM + 4];
    __shared__ float Bs[HBK][HBN + 4];
    int bm = blockIdx.y * HBM;
    int bn = blockIdx.x * HBN;
    int tid = threadIdx.x;
    int tm = (tid >> 4) * 8;
    int tn = (tid & 15) * 4;
    // acc[p][j]: rows (tm+2p, tm+2p+1) packed, col tn+j
    ull acc[4][4] = {};

    for (int k0 = 0; k0 < DM; k0 += HBK) {
        // Load A tile: 128 rows x 16 k, float2 global loads (DM even => 8B aligned)
        for (int idx = tid; idx < HBM * 8; idx += 256) {
            int m = idx >> 3, kp = idx & 7;
            int kk = k0 + 2 * kp;
            float2 v = make_float2(0.f, 0.f);
            if (kk < DM) v = *(const float2*)&X[(size_t)(bm + m) * DM + kk];
            As[2 * kp][m]     = v.x;
            As[2 * kp + 1][m] = v.y;
        }
        // Load B tile: 64 rows (n) x 16 k
        for (int idx = tid; idx < HBN * 8; idx += 256) {
            int n = idx >> 3, kp = idx & 7;
            int kk = k0 + 2 * kp;
            int gn = bn + n;
            float2 v = make_float2(0.f, 0.f);
            if (gn < DM && kk < DM) v = *(const float2*)&W[(size_t)gn * DM + kk];
            Bs[2 * kp][n]     = v.x;
            Bs[2 * kp + 1][n] = v.y;
        }
        __syncthreads();
#pragma unroll
        for (int k = 0; k < HBK; k++) {
            float4 a0 = *(const float4*)&As[k][tm];
            float4 a1 = *(const float4*)&As[k][tm + 4];
            float4 bv = *(const float4*)&Bs[k][tn];
            ull ap[4];
            ap[0] = pk2(a0.x, a0.y); ap[1] = pk2(a0.z, a0.w);
            ap[2] = pk2(a1.x, a1.y); ap[3] = pk2(a1.z, a1.w);
            float bb[4] = {bv.x, bv.y, bv.z, bv.w};
#pragma unroll
            for (int j = 0; j < 4; j++) {
                ull bd = pk2(bb[j], bb[j]);
#pragma unroll
                for (int p = 0; p < 4; p++) fma2(acc[p][j], ap[p], bd);
            }
        }
        __syncthreads();
    }

#pragma unroll
    for (int p = 0; p < 4; p++) {
        int m0 = bm + tm + 2 * p;
#pragma unroll
        for (int j = 0; j < 4; j++) {
            int n = bn + tn + j;
            if (n < DM) {
                float y0, y1;
                upk2(acc[p][j], y0, y1);
                float yy = y0 + bias[n];
                float g  = 1.f / (1.f + __expf(-yy));
                float xv = X[(size_t)m0 * DM + n];
                OUT[(size_t)m0 * DM + n] = g * fmaxf(yy, 0.f) + (1.f - g) * xv;
                yy = y1 + bias[n];
                g  = 1.f / (1.f + __expf(-yy));
                xv = X[(size_t)(m0 + 1) * DM + n];
                OUT[(size_t)(m0 + 1) * DM + n] = g * fmaxf(yy, 0.f) + (1.f - g) * xv;
            }
        }
    }
}

// ---------------------------------------------------------------------------
// 4) Self-attention. One block (512 thr) per (branch, b). f32x2 mainloops.
//    scores[i][j] = s1[i] + s2[j] + sum_d x[i,d]*w3[d]*x[j,d] + b
//    soft mask (-1e-9 on j>=len, still in softmax) like the reference.
//    Softmax fully in-warp: warp w owns rows 4w..4w+3 across all 64 cols.
// ---------------------------------------------------------------------------
__global__ __launch_bounds__(512) void attn_kernel(
        const int* __restrict__ q1_len, const int* __restrict__ q2_len,
        const float* __restrict__ attw, const float* __restrict__ attb,
        int it, int last, float* __restrict__ dout) {
    int batch = blockIdx.x;
    int r = batch >> 6, b = batch & 63;
    int len = (r ? q2_len : q1_len)[b];
    const float* aw = attw + it * (3 * DM);
    float ab = attb[it];
    float* X = g_x + (size_t)batch * 64 * DM;

    __shared__ float xsT[64][68];   // phase A: [d][row]; phase C reused row-major [row][d]
    __shared__ float xw[64][68];    // phase A: w3-scaled [d][row]; later probs^T [j][row]
    __shared__ float s1[64], s2[64];

    int tid  = threadIdx.x;
    int warp = tid >> 5, lane = tid & 31;
    int ti  = warp * 4;       // this warp's 4 rows
    int tj2 = lane * 2;       // this thread's 2 cols

    if (tid < 64) { s1[tid] = 0.f; s2[tid] = 0.f; }

    ull acc[4] = {0, 0, 0, 0};   // acc[i]: row ti+i, cols (tj2, tj2+1)

    // ---- Phase A: scores + s1/s2 over d-tiles ----
    for (int d0 = 0; d0 < DM; d0 += 64) {
        int dn = min(64, DM - d0);
        __syncthreads();
        for (int idx = tid; idx < 64 * 64; idx += 512) {
            int row = idx >> 6, d = idx & 63;
            float v  = (d < dn) ? X[row * DM + d0 + d] : 0.f;
            float wv = (d < dn) ? aw[2 * DM + d0 + d] : 0.f;
            xsT[d][row] = v;
            xw[d][row]  = v * wv;
        }
        __syncthreads();

        // s1/s2 partial dots: warp owns rows ti..ti+3
#pragma unroll
        for (int rr = 0; rr < 4; rr++) {
            int row = ti + rr;
            float a1 = 0.f, a2 = 0.f;
            for (int d = lane; d < dn; d += 32) {
                float xv = xsT[d][row];
                a1 += xv * aw[d0 + d];
                a2 += xv * aw[DM + d0 + d];
            }
#pragma unroll
            for (int off = 16; off > 0; off >>= 1) {
                a1 += __shfl_down_sync(0xffffffffu, a1, off);
                a2 += __shfl_down_sync(0xffffffffu, a2, off);
            }
            if (lane == 0) { s1[row] += a1; s2[row] += a2; }
        }

        // (x*w3) @ x^T partial: broadcast LDS.128 (rows) + LDS.64 (col pair)
#pragma unroll 4
        for (int d = 0; d < 64; d++) {
            float4 a4 = *(const float4*)&xsT[d][ti];
            ull bw = *(const ull*)&xw[d][tj2];
            fma2(acc[0], pk2(a4.x, a4.x), bw);
            fma2(acc[1], pk2(a4.y, a4.y), bw);
            fma2(acc[2], pk2(a4.z, a4.z), bw);
            fma2(acc[3], pk2(a4.w, a4.w), bw);
        }
    }
    __syncthreads();   // s1/s2 complete; xw reads done

    // ---- Phase B: softmax, in-warp (warp has rows ti..ti+3, all cols) ----
    {
        float2 s2p = *(const float2*)&s2[tj2];
#pragma unroll
        for (int i = 0; i < 4; i++) {
            int row = ti + i;
            float base = s1[row] + ab;
            float v0, v1;
            upk2(acc[i], v0, v1);
            v0 += base + s2p.x;
            v1 += base + s2p.y;
            float l0 = (tj2     < len) ? v0 : -1e-9f;
            float l1 = (tj2 + 1 < len) ? v1 : -1e-9f;
            float mx = fmaxf(l0, l1);
#pragma unroll
            for (int off = 16; off > 0; off >>= 1)
                mx = fmaxf(mx, __shfl_xor_sync(0xffffffffu, mx, off));
            float e0 = __expf(l0 - mx), e1 = __expf(l1 - mx);
            float s = e0 + e1;
#pragma unroll
            for (int off = 16; off > 0; off >>= 1)
                s += __shfl_xor_sync(0xffffffffu, s, off);
            float inv = 1.f / s;
            xw[tj2][row]     = e0 * inv;   // probs transposed: xw[j][row]
            xw[tj2 + 1][row] = e1 * inv;
        }
    }
    __syncthreads();

    // ---- Phase C: att = P @ x; out / residual. xsT reused row-major. ----
    float* xs = &xsT[0][0];  // xs[row*68 + d]
    for (int d0 = 0; d0 < DM; d0 += 64) {
        int dn = min(64, DM - d0);
        for (int idx = tid; idx < 64 * 32; idx += 512) {
            int row = idx >> 5, dp = idx & 31;
            float2 v = make_float2(0.f, 0.f);
            if (2 * dp < dn) v = *(const float2*)&X[row * DM + d0 + 2 * dp];
            *(float2*)&xs[row * 68 + 2 * dp] = v;
        }
        __syncthreads();
        ull acco[4] = {0, 0, 0, 0};   // acco[i]: row ti+i, d-cols (tj2, tj2+1)
#pragma unroll 4
        for (int j = 0; j < 64; j++) {
            float4 p4 = *(const float4*)&xw[j][ti];
            ull xv = *(const ull*)&xs[j * 68 + tj2];
            fma2(acco[0], pk2(p4.x, p4.x), xv);
            fma2(acco[1], pk2(p4.y, p4.y), xv);
            fma2(acco[2], pk2(p4.z, p4.z), xv);
            fma2(acco[3], pk2(p4.w, p4.w), xv);
        }
        int d = d0 + tj2;
#pragma unroll
        for (int i = 0; i < 4; i++) {
            int row = ti + i;
            float o0, o1;
            upk2(acco[i], o0, o1);
            if (last) {
                if (d < DM)     dout[((size_t)batch * 64 + row) * DM + d]     = o0;
                if (d + 1 < DM) dout[((size_t)batch * 64 + row) * DM + d + 1] = o1;
            } else {
                float2 xv = *(const float2*)&xs[row * 68 + tj2];
                if (d < DM)     X[row * DM + d]     = o0 + xv.x;
                if (d + 1 < DM) X[row * DM + d + 1] = o1 + xv.y;
            }
        }
        __syncthreads();
    }
}

// ---------------------------------------------------------------------------
extern "C" void kernel_launch(void* const* d_in, const int* in_sizes, int n_in,
                              void* d_out, int out_size) {
    const int*   q1     = (const int*)d_in[0];
    const int*   q2     = (const int*)d_in[1];
    const int*   q1_len = (const int*)d_in[2];
    const int*   q2_len = (const int*)d_in[3];
    const int*   q1c    = (const int*)d_in[4];
    const int*   q2c    = (const int*)d_in[5];
    const float* wemb   = (const float*)d_in[6];
    const float* cemb   = (const float*)d_in[7];
    const float* cw3    = (const float*)d_in[8];
    const float* cb3    = (const float*)d_in[9];
    const float* cw4    = (const float*)d_in[10];
    const float* cb4    = (const float*)d_in[11];
    const float* cw5    = (const float*)d_in[12];
    const float* cb5    = (const float*)d_in[13];
    const float* hw_w   = (const float*)d_in[14];
    const float* hw_b   = (const float*)d_in[15];
    const float* attw   = (const float*)d_in[16];
    const float* attb   = (const float*)d_in[17];
    float* out = (float*)d_out;

    precomp_kernel<<<(60000 + 255) / 256, 256>>>(cemb, cw3, cw4, cw5);
    embed_kernel<<<NTOK, 160>>>(q1, q2, q1c, q2c, wemb, cb3, cb4, cb5);
    highway_kernel<<<dim3(8, 64), 256>>>(0, hw_w, hw_b);   // g_x -> g_y
    highway_kernel<<<dim3(8, 64), 256>>>(1, hw_w, hw_b);   // g_y -> g_x
    attn_kernel<<<128, 512>>>(q1_len, q2_len, attw, attb, 0, 0, out);
    attn_kernel<<<128, 512>>>(q1_len, q2_len, attw, attb, 1, 1, out);
}